// round 13
// baseline (speedup 1.0000x reference)
#include <cuda_runtime.h>
#include <cuda_fp16.h>
#include <math.h>
#include <cstdint>

#define LSEQ   1024
#define NBATCH 64
#define NCH    64
#define NSTEP  1056          /* steps per strip: 1024 + 31 + pad */
#define NSP    528           /* step pairs per strip */
#define BIGC   1.0e10f
#define LOG2E  1.4426950408889634f
#define LN2F   0.6931471805599453f

/* Paired-step fp16 scratch: g_Dh[b][w][sp][l][2] holds D[32w+l][s-l]*log2(e)
   for s = 2sp, 2sp+1. 138 MB. Unwritten slots stay 0 (harmless). */
__device__ __half g_Dh[(size_t)NBATCH * 32 * NSP * 64];

__device__ __forceinline__ float ex2(float z) {
    float r; asm("ex2.approx.f32 %0, %1;" : "=f"(r) : "f"(z)); return r;
}
__device__ __forceinline__ float lg2(float z) {
    float r; asm("lg2.approx.f32 %0, %1;" : "=f"(r) : "f"(z)); return r;
}
__device__ __forceinline__ uint32_t f2tf32(float v) {
    uint32_t r; asm("cvt.rna.tf32.f32 %0, %1;" : "=r"(r) : "f"(v)); return r;
}
/* softmin in base-2 domain: -log2(2^-a + 2^-u + 2^-lf), 3 MUFU */
__device__ __forceinline__ float softmin3(float a, float u, float lf) {
    float mn1 = fminf(a, u);
    float mx1 = fmaxf(a, u);
    float m   = fminf(mn1, lf);
    float M   = fmaxf(mx1, lf);
    float med = fmaxf(mn1, fminf(mx1, lf));
    float e   = 1.0f + ex2(m - med) + ex2(m - M);
    return m - lg2(e);
}

/* ------------------------------------------------------------------ */
/* Kernel A: D = (x2 + y2 - 2*x.y^T) * log2(e) via tf32 mma.sync,     */
/* written (fp16, paired-step layout) into g_Dh. R8 structure.         */
/* ------------------------------------------------------------------ */
__global__ void __launch_bounds__(256)
compute_D_kernel(const float* __restrict__ x, const float* __restrict__ y) {
    const int b  = blockIdx.y;
    const int ti = blockIdx.x >> 4;
    const int tj = blockIdx.x & 15;
    const int i0 = ti * 64, j0 = tj * 64;

    __shared__ float sbuf[2 * 64 * 68];
    __shared__ float sx2[64], sy2[64];
    float* xs = sbuf;
    float* ys = sbuf + 64 * 68;

    const int tid = threadIdx.x;
    const float4* xb4 = (const float4*)(x + ((size_t)b * LSEQ + i0) * NCH);
    const float4* yb4 = (const float4*)(y + ((size_t)b * LSEQ + j0) * NCH);

#pragma unroll
    for (int k = 0; k < 4; k++) {
        int e = tid + 256 * k;
        int r = e >> 4, c4v = e & 15;
        float4 vx = xb4[r * 16 + c4v];
        float4 vy = yb4[r * 16 + c4v];
        vx.x = __uint_as_float(f2tf32(vx.x)); vx.y = __uint_as_float(f2tf32(vx.y));
        vx.z = __uint_as_float(f2tf32(vx.z)); vx.w = __uint_as_float(f2tf32(vx.w));
        vy.x = __uint_as_float(f2tf32(vy.x)); vy.y = __uint_as_float(f2tf32(vy.y));
        vy.z = __uint_as_float(f2tf32(vy.z)); vy.w = __uint_as_float(f2tf32(vy.w));
        *(float4*)&xs[r * 68 + c4v * 4] = vx;
        *(float4*)&ys[r * 68 + c4v * 4] = vy;
    }
    __syncthreads();

    if (tid < 64) {
        float s = 0.f;
#pragma unroll
        for (int c = 0; c < 64; c++) { float v = xs[tid * 68 + c]; s += v * v; }
        sx2[tid] = s;
    } else if (tid < 128) {
        int r = tid - 64;
        float s = 0.f;
#pragma unroll
        for (int c = 0; c < 64; c++) { float v = ys[r * 68 + c]; s += v * v; }
        sy2[r] = s;
    }
    __syncthreads();

    const int wrp  = tid >> 5, lane = tid & 31;
    const int wr   = wrp & 3, wc = wrp >> 2;
    const int r4   = lane >> 2, c4 = lane & 3;
    const float* As = xs + (wr * 16) * 68;
    const float* Bs = ys + (wc * 32) * 68;

    float cc[4][4];
#pragma unroll
    for (int nt = 0; nt < 4; nt++)
#pragma unroll
        for (int q = 0; q < 4; q++) cc[nt][q] = 0.f;

#pragma unroll
    for (int k0 = 0; k0 < 64; k0 += 8) {
        uint32_t a0 = __float_as_uint(As[(r4)     * 68 + k0 + c4]);
        uint32_t a1 = __float_as_uint(As[(r4 + 8) * 68 + k0 + c4]);
        uint32_t a2 = __float_as_uint(As[(r4)     * 68 + k0 + c4 + 4]);
        uint32_t a3 = __float_as_uint(As[(r4 + 8) * 68 + k0 + c4 + 4]);
#pragma unroll
        for (int nt = 0; nt < 4; nt++) {
            uint32_t b0 = __float_as_uint(Bs[(nt * 8 + r4) * 68 + k0 + c4]);
            uint32_t b1 = __float_as_uint(Bs[(nt * 8 + r4) * 68 + k0 + c4 + 4]);
            asm volatile(
                "mma.sync.aligned.m16n8k8.row.col.f32.tf32.tf32.f32 "
                "{%0,%1,%2,%3}, {%4,%5,%6,%7}, {%8,%9}, {%0,%1,%2,%3};"
                : "+f"(cc[nt][0]), "+f"(cc[nt][1]), "+f"(cc[nt][2]), "+f"(cc[nt][3])
                : "r"(a0), "r"(a1), "r"(a2), "r"(a3), "r"(b0), "r"(b1));
        }
    }
    __syncthreads();

    float* Dt = sbuf;                 /* Dt_T[jl][il], stride 67 */
    const int row0 = wr * 16 + r4;
#pragma unroll
    for (int nt = 0; nt < 4; nt++) {
        int colb = wc * 32 + nt * 8 + 2 * c4;
        Dt[colb * 67 + row0]           = (sx2[row0]     + sy2[colb]     - 2.0f * cc[nt][0]) * LOG2E;
        Dt[(colb + 1) * 67 + row0]     = (sx2[row0]     + sy2[colb + 1] - 2.0f * cc[nt][1]) * LOG2E;
        Dt[colb * 67 + row0 + 8]       = (sx2[row0 + 8] + sy2[colb]     - 2.0f * cc[nt][2]) * LOG2E;
        Dt[(colb + 1) * 67 + row0 + 8] = (sx2[row0 + 8] + sy2[colb + 1] - 2.0f * cc[nt][3]) * LOG2E;
    }
    __syncthreads();

    /* strip w = 2*ti + h owns rows 32h..32h+31 of this tile; lane l   */
    /* writes fp16 D[i0+32h+l][j0+so-l] at paired index                 */
    /* hbase + ((j0+so)>>1)*64 + lane*2 + ((j0+so)&1).                  */
    const int h  = wrp & 1;
    const int w4 = wrp >> 1;
    const size_t hbase = (size_t)(b * 32 + ti * 2 + h) * (NSP * 64);
    for (int so = w4; so < 95; so += 4) {
        int jl = so - lane;
        if (jl >= 0 && jl < 64) {
            int sg = j0 + so;
            g_Dh[hbase + (size_t)(sg >> 1) * 64 + lane * 2 + (sg & 1)] =
                __float2half_rn(Dt[jl * 67 + 32 * h + lane]);
        }
    }
}

/* ------------------------------------------------------------------ */
/* Kernel B: R8 structure — 32 warps x 1 row/lane, barrier-paced,      */
/* CH=8 / KOFF=5 (lag 40), unguarded body. D prefetch now 4x LDG.32    */
/* of half2 pairs per chunk (half the MIO ops), cvt off the chain.     */
/* ------------------------------------------------------------------ */
#define CH      8
#define NCHUNK  132                     /* 132*8 = 1056 >= 1055 steps */
#define KOFF    5
#define NROUNDS (KOFF * 31 + NCHUNK)    /* 287 */

__global__ void __launch_bounds__(1024)
sdtw_pipeline_kernel(float* __restrict__ out) {
    const int b   = blockIdx.x;
    const int tid = threadIdx.x;
    const int w   = tid >> 5;
    const int l   = tid & 31;

    __shared__ float rb[31][128];       /* boundary rings: rb[w] fed by warp w lane 31 */

    for (int e = tid; e < 31 * 128; e += 1024) ((float*)rb)[e] = BIGC;
    __syncthreads();

    float v1     = BIGC;                            /* left operand  */
    float u_prev = (w == 0 && l == 0) ? 0.0f : BIGC;/* diag operand  */
    float result = 0.0f;

    const __half2* dp2 = (const __half2*)g_Dh + (size_t)(b * 32 + w) * (NSP * 32) + l;
    float*         rbw = (w < 31) ? rb[w] : rb[0];
    const float*   rbr = (w > 0) ? rb[w - 1] : rb[0];

    float dv[CH];
    if (w == 0) {                        /* warp 0 preloads its chunk 0 */
#pragma unroll
        for (int p = 0; p < CH / 2; p++) {
            float2 f = __half22float2(dp2[(size_t)p * 32]);
            dv[2 * p] = f.x; dv[2 * p + 1] = f.y;
        }
    }

    for (int r = 0; r < NROUNDS; r++) {
        const int c  = r - KOFF * w;
        const int cn = c + 1;

        /* prefetch next chunk (consumed next round): 4 LDG.32 + cvt */
        float dn[CH];
        const bool pf = (cn >= 0) && (cn < NCHUNK);
        if (pf) {
            const __half2* dpn = dp2 + (size_t)(cn * (CH / 2)) * 32;
#pragma unroll
            for (int p = 0; p < CH / 2; p++) {
                float2 f = __half22float2(dpn[(size_t)p * 32]);
                dn[2 * p] = f.x; dn[2 * p + 1] = f.y;
            }
        }

        if (c >= 0 && c < NCHUNK) {
            const int sc = c * CH;
#pragma unroll
            for (int k = 0; k < CH; k++) {
                const int s = sc + k;
                float rv = rbr[(s + 1) & 127];              /* broadcast LDS */
                float u  = __shfl_up_sync(0xffffffffu, v1, 1);
                if (l == 0) u = (w == 0) ? BIGC : rv;
                float nv = dv[k] + softmin3(u_prev, u, v1);
                if (l == 31) {
                    if (w < 31) rbw[(s - 30) & 127] = nv;
                    else if (s == 1054) result = nv;        /* R[1024][1024] */
                }
                v1     = nv;
                u_prev = u;
            }
        }

        if (pf) {
#pragma unroll
            for (int k = 0; k < CH; k++) dv[k] = dn[k];
        }
        __syncthreads();
    }

    if (w == 31 && l == 31) out[b] = result * LN2F;
}

/* ------------------------------------------------------------------ */
extern "C" void kernel_launch(void* const* d_in, const int* in_sizes, int n_in,
                              void* d_out, int out_size) {
    (void)in_sizes; (void)n_in; (void)out_size;
    const float* x = (const float*)d_in[0];
    const float* y = (const float*)d_in[1];
    float* out = (float*)d_out;

    dim3 gridA(256, NBATCH);
    compute_D_kernel<<<gridA, 256>>>(x, y);
    sdtw_pipeline_kernel<<<NBATCH, 1024>>>(out);
}

// round 14
// speedup vs baseline: 1.5784x; 1.5784x over previous
#include <cuda_runtime.h>
#include <math.h>
#include <cstdint>

#define LSEQ   1024
#define NBATCH 64
#define NCH    64
#define NSTEP  1056          /* steps per strip: 1024 + 31 + pad */
#define BIGC   1.0e10f
#define LOG2E  1.4426950408889634f
#define LN2F   0.6931471805599453f

/* Strip-step-major scratch: g_D1[b][w][s][l] = D[32w+l][s-l] * log2(e).
   277 MB. Slots with s-l outside [0,1023] are never written and stay 0. */
__device__ float g_D1[(size_t)NBATCH * 32 * NSTEP * 32];

__device__ __forceinline__ float lg2(float z) {
    float r; asm("lg2.approx.f32 %0, %1;" : "=f"(r) : "f"(z)); return r;
}
__device__ __forceinline__ uint32_t f2tf32(float v) {
    uint32_t r; asm("cvt.rna.tf32.f32 %0, %1;" : "=r"(r) : "f"(v)); return r;
}
/* softmin in base-2 domain: -log2(2^-a + 2^-u + 2^-lf).
   The two sub-unity exponentials are packed into ONE ex2.approx.f16x2
   (args in [-inf,0]; f32->f16 saturates to -inf -> ex2 gives 0). MUFU
   ops per cell: 2 (was 3).                                            */
__device__ __forceinline__ float softmin3(float a, float u, float lf) {
    float mn1 = fminf(a, u);
    float mx1 = fmaxf(a, u);
    float m   = fminf(mn1, lf);
    float M   = fmaxf(mx1, lf);
    float med = fmaxf(mn1, fminf(mx1, lf));
    float t0  = m - med, t1 = m - M;
    uint32_t p, q;
    asm("cvt.rn.f16x2.f32 %0, %1, %2;" : "=r"(p) : "f"(t0), "f"(t1));
    asm("ex2.approx.f16x2 %0, %1;"     : "=r"(q) : "r"(p));
    float ea, eb;
    asm("{.reg .b16 l,h; mov.b32 {l,h}, %2; cvt.f32.f16 %0, l; cvt.f32.f16 %1, h;}"
        : "=f"(ea), "=f"(eb) : "r"(q));
    float e = 1.0f + (ea + eb);
    return m - lg2(e);
}

/* ------------------------------------------------------------------ */
/* Kernel A: D = (x2 + y2 - 2*x.y^T) * log2(e) via tf32 mma.sync,     */
/* written into the strip-step-major layout g_D1. (R8-exact)           */
/* ------------------------------------------------------------------ */
__global__ void __launch_bounds__(256)
compute_D_kernel(const float* __restrict__ x, const float* __restrict__ y) {
    const int b  = blockIdx.y;
    const int ti = blockIdx.x >> 4;
    const int tj = blockIdx.x & 15;
    const int i0 = ti * 64, j0 = tj * 64;

    __shared__ float sbuf[2 * 64 * 68];
    __shared__ float sx2[64], sy2[64];
    float* xs = sbuf;
    float* ys = sbuf + 64 * 68;

    const int tid = threadIdx.x;
    const float4* xb4 = (const float4*)(x + ((size_t)b * LSEQ + i0) * NCH);
    const float4* yb4 = (const float4*)(y + ((size_t)b * LSEQ + j0) * NCH);

#pragma unroll
    for (int k = 0; k < 4; k++) {
        int e = tid + 256 * k;
        int r = e >> 4, c4v = e & 15;
        float4 vx = xb4[r * 16 + c4v];
        float4 vy = yb4[r * 16 + c4v];
        vx.x = __uint_as_float(f2tf32(vx.x)); vx.y = __uint_as_float(f2tf32(vx.y));
        vx.z = __uint_as_float(f2tf32(vx.z)); vx.w = __uint_as_float(f2tf32(vx.w));
        vy.x = __uint_as_float(f2tf32(vy.x)); vy.y = __uint_as_float(f2tf32(vy.y));
        vy.z = __uint_as_float(f2tf32(vy.z)); vy.w = __uint_as_float(f2tf32(vy.w));
        *(float4*)&xs[r * 68 + c4v * 4] = vx;
        *(float4*)&ys[r * 68 + c4v * 4] = vy;
    }
    __syncthreads();

    if (tid < 64) {
        float s = 0.f;
#pragma unroll
        for (int c = 0; c < 64; c++) { float v = xs[tid * 68 + c]; s += v * v; }
        sx2[tid] = s;
    } else if (tid < 128) {
        int r = tid - 64;
        float s = 0.f;
#pragma unroll
        for (int c = 0; c < 64; c++) { float v = ys[r * 68 + c]; s += v * v; }
        sy2[r] = s;
    }
    __syncthreads();

    const int wrp  = tid >> 5, lane = tid & 31;
    const int wr   = wrp & 3, wc = wrp >> 2;
    const int r4   = lane >> 2, c4 = lane & 3;
    const float* As = xs + (wr * 16) * 68;
    const float* Bs = ys + (wc * 32) * 68;

    float cc[4][4];
#pragma unroll
    for (int nt = 0; nt < 4; nt++)
#pragma unroll
        for (int q = 0; q < 4; q++) cc[nt][q] = 0.f;

#pragma unroll
    for (int k0 = 0; k0 < 64; k0 += 8) {
        uint32_t a0 = __float_as_uint(As[(r4)     * 68 + k0 + c4]);
        uint32_t a1 = __float_as_uint(As[(r4 + 8) * 68 + k0 + c4]);
        uint32_t a2 = __float_as_uint(As[(r4)     * 68 + k0 + c4 + 4]);
        uint32_t a3 = __float_as_uint(As[(r4 + 8) * 68 + k0 + c4 + 4]);
#pragma unroll
        for (int nt = 0; nt < 4; nt++) {
            uint32_t b0 = __float_as_uint(Bs[(nt * 8 + r4) * 68 + k0 + c4]);
            uint32_t b1 = __float_as_uint(Bs[(nt * 8 + r4) * 68 + k0 + c4 + 4]);
            asm volatile(
                "mma.sync.aligned.m16n8k8.row.col.f32.tf32.tf32.f32 "
                "{%0,%1,%2,%3}, {%4,%5,%6,%7}, {%8,%9}, {%0,%1,%2,%3};"
                : "+f"(cc[nt][0]), "+f"(cc[nt][1]), "+f"(cc[nt][2]), "+f"(cc[nt][3])
                : "r"(a0), "r"(a1), "r"(a2), "r"(a3), "r"(b0), "r"(b1));
        }
    }
    __syncthreads();

    float* Dt = sbuf;                 /* Dt_T[jl][il], stride 67 */
    const int row0 = wr * 16 + r4;
#pragma unroll
    for (int nt = 0; nt < 4; nt++) {
        int colb = wc * 32 + nt * 8 + 2 * c4;
        Dt[colb * 67 + row0]           = (sx2[row0]     + sy2[colb]     - 2.0f * cc[nt][0]) * LOG2E;
        Dt[(colb + 1) * 67 + row0]     = (sx2[row0]     + sy2[colb + 1] - 2.0f * cc[nt][1]) * LOG2E;
        Dt[colb * 67 + row0 + 8]       = (sx2[row0 + 8] + sy2[colb]     - 2.0f * cc[nt][2]) * LOG2E;
        Dt[(colb + 1) * 67 + row0 + 8] = (sx2[row0 + 8] + sy2[colb + 1] - 2.0f * cc[nt][3]) * LOG2E;
    }
    __syncthreads();

    /* strip w = 2*ti + h owns rows 32h..32h+31 of this tile; lane l   */
    /* writes D[i0+32h+l][j0+so-l] at g_D1[b][w][j0+so][l].             */
    const int h  = wrp & 1;
    const int w4 = wrp >> 1;
    const size_t gbase = ((size_t)(b * 32 + ti * 2 + h) * NSTEP + j0) * 32;
    for (int so = w4; so < 95; so += 4) {
        int jl = so - lane;
        if (jl >= 0 && jl < 64) {
            g_D1[gbase + (size_t)so * 32 + lane] = Dt[jl * 67 + 32 * h + lane];
        }
    }
}

/* ------------------------------------------------------------------ */
/* Kernel B: R8 structure — 32 warps x 1 row/lane, barrier-paced,      */
/* CH=8 / KOFF=5 (lag 40), fp32 D double-buffered prefetch (loads      */
/* consumed AFTER compute -> latency hidden), unguarded body,          */
/* f16x2-packed ex2 (2 MUFU per cell).                                 */
/* ------------------------------------------------------------------ */
#define CH      8
#define NCHUNK  132                     /* 132*8 = 1056 >= 1055 steps */
#define KOFF    5
#define NROUNDS (KOFF * 31 + NCHUNK)    /* 287 */

__global__ void __launch_bounds__(1024)
sdtw_pipeline_kernel(float* __restrict__ out) {
    const int b   = blockIdx.x;
    const int tid = threadIdx.x;
    const int w   = tid >> 5;
    const int l   = tid & 31;

    __shared__ float rb[31][128];       /* boundary rings: rb[w] fed by warp w lane 31 */

    for (int e = tid; e < 31 * 128; e += 1024) ((float*)rb)[e] = BIGC;
    __syncthreads();

    float v1     = BIGC;                            /* left operand  */
    float u_prev = (w == 0 && l == 0) ? 0.0f : BIGC;/* diag operand  */
    float result = 0.0f;

    const float* dp  = g_D1 + ((size_t)(b * 32 + w) * NSTEP) * 32 + l;
    float*       rbw = (w < 31) ? rb[w] : rb[0];
    const float* rbr = (w > 0) ? rb[w - 1] : rb[0];

    float dv[CH];
    if (w == 0) {                        /* warp 0 preloads its chunk 0 */
#pragma unroll
        for (int k = 0; k < CH; k++) dv[k] = dp[(size_t)k * 32];
    }

    for (int r = 0; r < NROUNDS; r++) {
        const int c  = r - KOFF * w;
        const int cn = c + 1;

        /* prefetch next chunk (consumed next round) */
        float dn[CH];
        const bool pf = (cn >= 0) && (cn < NCHUNK);
        if (pf) {
            const float* dpn = dp + (size_t)(cn * CH) * 32;
#pragma unroll
            for (int k = 0; k < CH; k++) dn[k] = dpn[(size_t)k * 32];
        }

        if (c >= 0 && c < NCHUNK) {
            const int sc = c * CH;
#pragma unroll
            for (int k = 0; k < CH; k++) {
                const int s = sc + k;
                float rv = rbr[(s + 1) & 127];              /* broadcast LDS */
                float u  = __shfl_up_sync(0xffffffffu, v1, 1);
                if (l == 0) u = (w == 0) ? BIGC : rv;
                float nv = dv[k] + softmin3(u_prev, u, v1);
                if (l == 31) {
                    if (w < 31) rbw[(s - 30) & 127] = nv;
                    else if (s == 1054) result = nv;        /* R[1024][1024] */
                }
                v1     = nv;
                u_prev = u;
            }
        }

        if (pf) {
#pragma unroll
            for (int k = 0; k < CH; k++) dv[k] = dn[k];
        }
        __syncthreads();
    }

    if (w == 31 && l == 31) out[b] = result * LN2F;
}

/* ------------------------------------------------------------------ */
extern "C" void kernel_launch(void* const* d_in, const int* in_sizes, int n_in,
                              void* d_out, int out_size) {
    (void)in_sizes; (void)n_in; (void)out_size;
    const float* x = (const float*)d_in[0];
    const float* y = (const float*)d_in[1];
    float* out = (float*)d_out;

    dim3 gridA(256, NBATCH);
    compute_D_kernel<<<gridA, 256>>>(x, y);
    sdtw_pipeline_kernel<<<NBATCH, 1024>>>(out);
}

// round 15
// speedup vs baseline: 1.7180x; 1.0885x over previous
#include <cuda_runtime.h>
#include <math.h>
#include <cstdint>

#define LSEQ   1024
#define NBATCH 64
#define NCH    64
#define NSTEP  1056          /* steps per strip: 1024 + 31 + pad */
#define BIGC   1.0e10f
#define LOG2E  1.4426950408889634f
#define LN2F   0.6931471805599453f

/* Strip-step-major scratch: g_D1[b][w][s][l] = D[32w+l][s-l] * log2(e).
   277 MB. Slots with s-l outside [0,1023] are never written and stay 0. */
__device__ float g_D1[(size_t)NBATCH * 32 * NSTEP * 32];

__device__ __forceinline__ float ex2(float z) {
    float r; asm("ex2.approx.f32 %0, %1;" : "=f"(r) : "f"(z)); return r;
}
__device__ __forceinline__ float lg2(float z) {
    float r; asm("lg2.approx.f32 %0, %1;" : "=f"(r) : "f"(z)); return r;
}
__device__ __forceinline__ uint32_t f2tf32(float v) {
    uint32_t r; asm("cvt.rna.tf32.f32 %0, %1;" : "=r"(r) : "f"(v)); return r;
}
/* softmin in base-2 domain: -log2(2^-a + 2^-u + 2^-lf), 3 MUFU (R8) */
__device__ __forceinline__ float softmin3(float a, float u, float lf) {
    float mn1 = fminf(a, u);
    float mx1 = fmaxf(a, u);
    float m   = fminf(mn1, lf);
    float M   = fmaxf(mx1, lf);
    float med = fmaxf(mn1, fminf(mx1, lf));
    float e   = 1.0f + ex2(m - med) + ex2(m - M);
    return m - lg2(e);
}

/* ------------------------------------------------------------------ */
/* Kernel A: D = (x2 + y2 - 2*x.y^T) * log2(e) via tf32 mma.sync,     */
/* 128x128 tiles (4096 CTAs): 2x less L2 read traffic, 4x fewer CTAs. */
/* Dynamic smem: xs[128][68] | ys[128][68], reused as Dt_T[128][131].  */
/* ------------------------------------------------------------------ */
__global__ void __launch_bounds__(256)
compute_D_kernel(const float* __restrict__ x, const float* __restrict__ y) {
    extern __shared__ float sbuf[];       /* 17408 floats = 69632 B */
    __shared__ float sx2[128], sy2[128];

    const int b  = blockIdx.y;
    const int ti = blockIdx.x >> 3;       /* 0..7 */
    const int tj = blockIdx.x & 7;        /* 0..7 */
    const int i0 = ti * 128, j0 = tj * 128;

    float* xs = sbuf;                     /* [128][68] */
    float* ys = sbuf + 128 * 68;          /* [128][68] */

    const int tid = threadIdx.x;
    const float4* xb4 = (const float4*)(x + ((size_t)b * LSEQ + i0) * NCH);
    const float4* yb4 = (const float4*)(y + ((size_t)b * LSEQ + j0) * NCH);

#pragma unroll
    for (int k = 0; k < 8; k++) {
        int e = tid + 256 * k;            /* 0..2047 */
        int r = e >> 4, c4v = e & 15;
        float4 vx = xb4[r * 16 + c4v];
        float4 vy = yb4[r * 16 + c4v];
        vx.x = __uint_as_float(f2tf32(vx.x)); vx.y = __uint_as_float(f2tf32(vx.y));
        vx.z = __uint_as_float(f2tf32(vx.z)); vx.w = __uint_as_float(f2tf32(vx.w));
        vy.x = __uint_as_float(f2tf32(vy.x)); vy.y = __uint_as_float(f2tf32(vy.y));
        vy.z = __uint_as_float(f2tf32(vy.z)); vy.w = __uint_as_float(f2tf32(vy.w));
        *(float4*)&xs[r * 68 + c4v * 4] = vx;
        *(float4*)&ys[r * 68 + c4v * 4] = vy;
    }
    __syncthreads();

    if (tid < 128) {
        float s = 0.f;
#pragma unroll
        for (int c = 0; c < 64; c++) { float v = xs[tid * 68 + c]; s += v * v; }
        sx2[tid] = s;
    } else {
        int r = tid - 128;
        float s = 0.f;
#pragma unroll
        for (int c = 0; c < 64; c++) { float v = ys[r * 68 + c]; s += v * v; }
        sy2[r] = s;
    }
    __syncthreads();

    /* 8 warps: warp wr owns rows [16wr, 16wr+16) x all 128 cols */
    const int wrp  = tid >> 5, lane = tid & 31;
    const int r4   = lane >> 2, c4 = lane & 3;
    const float* As = xs + (wrp * 16) * 68;
    const float* Bs = ys;

    float cc[16][4];
#pragma unroll
    for (int nt = 0; nt < 16; nt++)
#pragma unroll
        for (int q = 0; q < 4; q++) cc[nt][q] = 0.f;

#pragma unroll
    for (int k0 = 0; k0 < 64; k0 += 8) {
        uint32_t a0 = __float_as_uint(As[(r4)     * 68 + k0 + c4]);
        uint32_t a1 = __float_as_uint(As[(r4 + 8) * 68 + k0 + c4]);
        uint32_t a2 = __float_as_uint(As[(r4)     * 68 + k0 + c4 + 4]);
        uint32_t a3 = __float_as_uint(As[(r4 + 8) * 68 + k0 + c4 + 4]);
#pragma unroll
        for (int nt = 0; nt < 16; nt++) {
            uint32_t b0 = __float_as_uint(Bs[(nt * 8 + r4) * 68 + k0 + c4]);
            uint32_t b1 = __float_as_uint(Bs[(nt * 8 + r4) * 68 + k0 + c4 + 4]);
            asm volatile(
                "mma.sync.aligned.m16n8k8.row.col.f32.tf32.tf32.f32 "
                "{%0,%1,%2,%3}, {%4,%5,%6,%7}, {%8,%9}, {%0,%1,%2,%3};"
                : "+f"(cc[nt][0]), "+f"(cc[nt][1]), "+f"(cc[nt][2]), "+f"(cc[nt][3])
                : "r"(a0), "r"(a1), "r"(a2), "r"(a3), "r"(b0), "r"(b1));
        }
    }
    __syncthreads();                  /* xs/ys dead -> reuse as Dt_T */

    float* Dt = sbuf;                 /* Dt_T[jl][il], stride 131 */
    const int row0 = wrp * 16 + r4;
#pragma unroll
    for (int nt = 0; nt < 16; nt++) {
        int colb = nt * 8 + 2 * c4;
        Dt[colb * 131 + row0]           = (sx2[row0]     + sy2[colb]     - 2.0f * cc[nt][0]) * LOG2E;
        Dt[(colb + 1) * 131 + row0]     = (sx2[row0]     + sy2[colb + 1] - 2.0f * cc[nt][1]) * LOG2E;
        Dt[colb * 131 + row0 + 8]       = (sx2[row0 + 8] + sy2[colb]     - 2.0f * cc[nt][2]) * LOG2E;
        Dt[(colb + 1) * 131 + row0 + 8] = (sx2[row0 + 8] + sy2[colb + 1] - 2.0f * cc[nt][3]) * LOG2E;
    }
    __syncthreads();

    /* strip w = 4*ti + h (h=0..3) owns rows 32h..32h+31 of this tile; */
    /* lane l writes D[i0+32h+l][j0+so-l] at g_D1[b][w][j0+so][l].      */
    const int h  = wrp & 3;
    const int w4 = wrp >> 2;          /* 0..1 */
    const size_t gbase = ((size_t)(b * 32 + ti * 4 + h) * NSTEP + j0) * 32;
    for (int so = w4; so < 159; so += 2) {
        int jl = so - lane;
        if (jl >= 0 && jl < 128) {
            g_D1[gbase + (size_t)so * 32 + lane] = Dt[jl * 131 + 32 * h + lane];
        }
    }
}

/* ------------------------------------------------------------------ */
/* Kernel B: R8-exact — 32 warps x 1 row/lane, barrier-paced,          */
/* CH=8 / KOFF=5 (lag 40), fp32 D double-buffered prefetch, unguarded. */
/* ------------------------------------------------------------------ */
#define CH      8
#define NCHUNK  132                     /* 132*8 = 1056 >= 1055 steps */
#define KOFF    5
#define NROUNDS (KOFF * 31 + NCHUNK)    /* 287 */

__global__ void __launch_bounds__(1024)
sdtw_pipeline_kernel(float* __restrict__ out) {
    const int b   = blockIdx.x;
    const int tid = threadIdx.x;
    const int w   = tid >> 5;
    const int l   = tid & 31;

    __shared__ float rb[31][128];       /* boundary rings: rb[w] fed by warp w lane 31 */

    for (int e = tid; e < 31 * 128; e += 1024) ((float*)rb)[e] = BIGC;
    __syncthreads();

    float v1     = BIGC;                            /* left operand  */
    float u_prev = (w == 0 && l == 0) ? 0.0f : BIGC;/* diag operand  */
    float result = 0.0f;

    const float* dp  = g_D1 + ((size_t)(b * 32 + w) * NSTEP) * 32 + l;
    float*       rbw = (w < 31) ? rb[w] : rb[0];
    const float* rbr = (w > 0) ? rb[w - 1] : rb[0];

    float dv[CH];
    if (w == 0) {                        /* warp 0 preloads its chunk 0 */
#pragma unroll
        for (int k = 0; k < CH; k++) dv[k] = dp[(size_t)k * 32];
    }

    for (int r = 0; r < NROUNDS; r++) {
        const int c  = r - KOFF * w;
        const int cn = c + 1;

        /* prefetch next chunk (consumed next round) */
        float dn[CH];
        const bool pf = (cn >= 0) && (cn < NCHUNK);
        if (pf) {
            const float* dpn = dp + (size_t)(cn * CH) * 32;
#pragma unroll
            for (int k = 0; k < CH; k++) dn[k] = dpn[(size_t)k * 32];
        }

        if (c >= 0 && c < NCHUNK) {
            const int sc = c * CH;
#pragma unroll
            for (int k = 0; k < CH; k++) {
                const int s = sc + k;
                float rv = rbr[(s + 1) & 127];              /* broadcast LDS */
                float u  = __shfl_up_sync(0xffffffffu, v1, 1);
                if (l == 0) u = (w == 0) ? BIGC : rv;
                float nv = dv[k] + softmin3(u_prev, u, v1);
                if (l == 31) {
                    if (w < 31) rbw[(s - 30) & 127] = nv;
                    else if (s == 1054) result = nv;        /* R[1024][1024] */
                }
                v1     = nv;
                u_prev = u;
            }
        }

        if (pf) {
#pragma unroll
            for (int k = 0; k < CH; k++) dv[k] = dn[k];
        }
        __syncthreads();
    }

    if (w == 31 && l == 31) out[b] = result * LN2F;
}

/* ------------------------------------------------------------------ */
extern "C" void kernel_launch(void* const* d_in, const int* in_sizes, int n_in,
                              void* d_out, int out_size) {
    (void)in_sizes; (void)n_in; (void)out_size;
    const float* x = (const float*)d_in[0];
    const float* y = (const float*)d_in[1];
    float* out = (float*)d_out;

    static int smem_set = 0;
    const int smem_b = 2 * 128 * 68 * (int)sizeof(float);   /* 69632 B */
    if (!smem_set) {
        cudaFuncSetAttribute(compute_D_kernel,
                             cudaFuncAttributeMaxDynamicSharedMemorySize, smem_b);
        smem_set = 1;
    }

    dim3 gridA(64, NBATCH);
    compute_D_kernel<<<gridA, 256, smem_b>>>(x, y);
    sdtw_pipeline_kernel<<<NBATCH, 1024>>>(out);
}

// round 16
// speedup vs baseline: 1.7828x; 1.0377x over previous
#include <cuda_runtime.h>
#include <math.h>
#include <cstdint>

#define LSEQ   1024
#define NBATCH 64
#define NCH    64
#define NSPG   264           /* step groups per strip: 264*4 = 1056 steps */
#define BIGC   1.0e10f
#define LOG2E  1.4426950408889634f
#define LN2F   0.6931471805599453f

/* Group-packed strip scratch: g_D4[b][w][sp][l][4] holds
   D[32w+l][(4sp+q)-l]*log2(e) for q=0..3. 277 MB. Unwritten slots stay 0. */
__device__ float g_D4[(size_t)NBATCH * 32 * NSPG * 128];

__device__ __forceinline__ float ex2(float z) {
    float r; asm("ex2.approx.f32 %0, %1;" : "=f"(r) : "f"(z)); return r;
}
__device__ __forceinline__ float lg2(float z) {
    float r; asm("lg2.approx.f32 %0, %1;" : "=f"(r) : "f"(z)); return r;
}
__device__ __forceinline__ uint32_t f2tf32(float v) {
    uint32_t r; asm("cvt.rna.tf32.f32 %0, %1;" : "=r"(r) : "f"(v)); return r;
}
/* softmin in base-2 domain: -log2(2^-a + 2^-u + 2^-lf), 3 MUFU (R8) */
__device__ __forceinline__ float softmin3(float a, float u, float lf) {
    float mn1 = fminf(a, u);
    float mx1 = fmaxf(a, u);
    float m   = fminf(mn1, lf);
    float M   = fmaxf(mx1, lf);
    float med = fmaxf(mn1, fminf(mx1, lf));
    float e   = 1.0f + ex2(m - med) + ex2(m - M);
    return m - lg2(e);
}

/* ------------------------------------------------------------------ */
/* Kernel A: D = (x2 + y2 - 2*x.y^T) * log2(e) via tf32 mma.sync,     */
/* 128x128 tiles; scatter writes float4 step-groups (STG.128).         */
/* ------------------------------------------------------------------ */
__global__ void __launch_bounds__(256)
compute_D_kernel(const float* __restrict__ x, const float* __restrict__ y) {
    extern __shared__ float sbuf[];       /* 17408 floats = 69632 B */
    __shared__ float sx2[128], sy2[128];

    const int b  = blockIdx.y;
    const int ti = blockIdx.x >> 3;       /* 0..7 */
    const int tj = blockIdx.x & 7;        /* 0..7 */
    const int i0 = ti * 128, j0 = tj * 128;

    float* xs = sbuf;                     /* [128][68] */
    float* ys = sbuf + 128 * 68;          /* [128][68] */

    const int tid = threadIdx.x;
    const float4* xb4 = (const float4*)(x + ((size_t)b * LSEQ + i0) * NCH);
    const float4* yb4 = (const float4*)(y + ((size_t)b * LSEQ + j0) * NCH);

#pragma unroll
    for (int k = 0; k < 8; k++) {
        int e = tid + 256 * k;            /* 0..2047 */
        int r = e >> 4, c4v = e & 15;
        float4 vx = xb4[r * 16 + c4v];
        float4 vy = yb4[r * 16 + c4v];
        vx.x = __uint_as_float(f2tf32(vx.x)); vx.y = __uint_as_float(f2tf32(vx.y));
        vx.z = __uint_as_float(f2tf32(vx.z)); vx.w = __uint_as_float(f2tf32(vx.w));
        vy.x = __uint_as_float(f2tf32(vy.x)); vy.y = __uint_as_float(f2tf32(vy.y));
        vy.z = __uint_as_float(f2tf32(vy.z)); vy.w = __uint_as_float(f2tf32(vy.w));
        *(float4*)&xs[r * 68 + c4v * 4] = vx;
        *(float4*)&ys[r * 68 + c4v * 4] = vy;
    }
    __syncthreads();

    if (tid < 128) {
        float s = 0.f;
#pragma unroll
        for (int c = 0; c < 64; c++) { float v = xs[tid * 68 + c]; s += v * v; }
        sx2[tid] = s;
    } else {
        int r = tid - 128;
        float s = 0.f;
#pragma unroll
        for (int c = 0; c < 64; c++) { float v = ys[r * 68 + c]; s += v * v; }
        sy2[r] = s;
    }
    __syncthreads();

    /* 8 warps: warp wrp owns rows [16wrp, 16wrp+16) x all 128 cols */
    const int wrp  = tid >> 5, lane = tid & 31;
    const int r4   = lane >> 2, c4 = lane & 3;
    const float* As = xs + (wrp * 16) * 68;
    const float* Bs = ys;

    float cc[16][4];
#pragma unroll
    for (int nt = 0; nt < 16; nt++)
#pragma unroll
        for (int q = 0; q < 4; q++) cc[nt][q] = 0.f;

#pragma unroll
    for (int k0 = 0; k0 < 64; k0 += 8) {
        uint32_t a0 = __float_as_uint(As[(r4)     * 68 + k0 + c4]);
        uint32_t a1 = __float_as_uint(As[(r4 + 8) * 68 + k0 + c4]);
        uint32_t a2 = __float_as_uint(As[(r4)     * 68 + k0 + c4 + 4]);
        uint32_t a3 = __float_as_uint(As[(r4 + 8) * 68 + k0 + c4 + 4]);
#pragma unroll
        for (int nt = 0; nt < 16; nt++) {
            uint32_t b0 = __float_as_uint(Bs[(nt * 8 + r4) * 68 + k0 + c4]);
            uint32_t b1 = __float_as_uint(Bs[(nt * 8 + r4) * 68 + k0 + c4 + 4]);
            asm volatile(
                "mma.sync.aligned.m16n8k8.row.col.f32.tf32.tf32.f32 "
                "{%0,%1,%2,%3}, {%4,%5,%6,%7}, {%8,%9}, {%0,%1,%2,%3};"
                : "+f"(cc[nt][0]), "+f"(cc[nt][1]), "+f"(cc[nt][2]), "+f"(cc[nt][3])
                : "r"(a0), "r"(a1), "r"(a2), "r"(a3), "r"(b0), "r"(b1));
        }
    }
    __syncthreads();                  /* xs/ys dead -> reuse as Dt_T */

    float* Dt = sbuf;                 /* Dt_T[jl][il], stride 131 */
    const int row0 = wrp * 16 + r4;
#pragma unroll
    for (int nt = 0; nt < 16; nt++) {
        int colb = nt * 8 + 2 * c4;
        Dt[colb * 131 + row0]           = (sx2[row0]     + sy2[colb]     - 2.0f * cc[nt][0]) * LOG2E;
        Dt[(colb + 1) * 131 + row0]     = (sx2[row0]     + sy2[colb + 1] - 2.0f * cc[nt][1]) * LOG2E;
        Dt[colb * 131 + row0 + 8]       = (sx2[row0 + 8] + sy2[colb]     - 2.0f * cc[nt][2]) * LOG2E;
        Dt[(colb + 1) * 131 + row0 + 8] = (sx2[row0 + 8] + sy2[colb + 1] - 2.0f * cc[nt][3]) * LOG2E;
    }
    __syncthreads();

    /* strip w = 4*ti + h (h=0..3) owns rows 32h..32h+31 of this tile.  */
    /* Step-group G covers so = 4G..4G+3; lane l writes float4 when the */
    /* whole group is tile-interior, else guarded scalar stores.        */
    const int h  = wrp & 3;
    const int w4 = wrp >> 2;          /* 0..1 */
    const size_t gbase = ((size_t)(b * 32 + ti * 4 + h) * NSPG + (j0 >> 2)) * 128;
    for (int G = w4; G < 40; G += 2) {
        const int jl0 = 4 * G - lane;
        float* dst = g_D4 + gbase + (size_t)G * 128 + lane * 4;
        if (jl0 >= 0 && jl0 <= 124) {
            float4 v;
            v.x = Dt[(jl0 + 0) * 131 + 32 * h + lane];
            v.y = Dt[(jl0 + 1) * 131 + 32 * h + lane];
            v.z = Dt[(jl0 + 2) * 131 + 32 * h + lane];
            v.w = Dt[(jl0 + 3) * 131 + 32 * h + lane];
            *(float4*)dst = v;
        } else {
#pragma unroll
            for (int q = 0; q < 4; q++) {
                int jl = jl0 + q;
                if (jl >= 0 && jl < 128)
                    dst[q] = Dt[jl * 131 + 32 * h + lane];
            }
        }
    }
}

/* ------------------------------------------------------------------ */
/* Kernel B: R8 structure — 32 warps x 1 row/lane, barrier-paced,      */
/* CH=8 / KOFF=5 (lag 40), unguarded body. D prefetch is now           */
/* 2x LDG.128 per chunk (float4 step-groups), consumed only by the     */
/* post-compute register copy (latency stays hidden).                  */
/* ------------------------------------------------------------------ */
#define CH      8
#define NCHUNK  132                     /* 132*8 = 1056 >= 1055 steps */
#define KOFF    5
#define NROUNDS (KOFF * 31 + NCHUNK)    /* 287 */

__global__ void __launch_bounds__(1024)
sdtw_pipeline_kernel(float* __restrict__ out) {
    const int b   = blockIdx.x;
    const int tid = threadIdx.x;
    const int w   = tid >> 5;
    const int l   = tid & 31;

    __shared__ float rb[31][128];       /* boundary rings: rb[w] fed by warp w lane 31 */

    for (int e = tid; e < 31 * 128; e += 1024) ((float*)rb)[e] = BIGC;
    __syncthreads();

    float v1     = BIGC;                            /* left operand  */
    float u_prev = (w == 0 && l == 0) ? 0.0f : BIGC;/* diag operand  */
    float result = 0.0f;

    /* float4 view: one group = 32 float4s; lane l owns float4 #l */
    const float4* dp4 = (const float4*)g_D4 + (size_t)(b * 32 + w) * (NSPG * 32) + l;
    float*       rbw = (w < 31) ? rb[w] : rb[0];
    const float* rbr = (w > 0) ? rb[w - 1] : rb[0];

    float dv[CH];
    if (w == 0) {                        /* warp 0 preloads its chunk 0 */
        float4 a0 = dp4[0];
        float4 a1 = dp4[32];
        dv[0] = a0.x; dv[1] = a0.y; dv[2] = a0.z; dv[3] = a0.w;
        dv[4] = a1.x; dv[5] = a1.y; dv[6] = a1.z; dv[7] = a1.w;
    }

    for (int r = 0; r < NROUNDS; r++) {
        const int c  = r - KOFF * w;
        const int cn = c + 1;

        /* prefetch next chunk: 2 LDG.128 (consumed next round) */
        float4 n0, n1;
        const bool pf = (cn >= 0) && (cn < NCHUNK);
        if (pf) {
            n0 = dp4[(size_t)(2 * cn) * 32];
            n1 = dp4[(size_t)(2 * cn + 1) * 32];
        }

        if (c >= 0 && c < NCHUNK) {
            const int sc = c * CH;
#pragma unroll
            for (int k = 0; k < CH; k++) {
                const int s = sc + k;
                float rv = rbr[(s + 1) & 127];              /* broadcast LDS */
                float u  = __shfl_up_sync(0xffffffffu, v1, 1);
                if (l == 0) u = (w == 0) ? BIGC : rv;
                float nv = dv[k] + softmin3(u_prev, u, v1);
                if (l == 31) {
                    if (w < 31) rbw[(s - 30) & 127] = nv;
                    else if (s == 1054) result = nv;        /* R[1024][1024] */
                }
                v1     = nv;
                u_prev = u;
            }
        }

        if (pf) {
            dv[0] = n0.x; dv[1] = n0.y; dv[2] = n0.z; dv[3] = n0.w;
            dv[4] = n1.x; dv[5] = n1.y; dv[6] = n1.z; dv[7] = n1.w;
        }
        __syncthreads();
    }

    if (w == 31 && l == 31) out[b] = result * LN2F;
}

/* ------------------------------------------------------------------ */
extern "C" void kernel_launch(void* const* d_in, const int* in_sizes, int n_in,
                              void* d_out, int out_size) {
    (void)in_sizes; (void)n_in; (void)out_size;
    const float* x = (const float*)d_in[0];
    const float* y = (const float*)d_in[1];
    float* out = (float*)d_out;

    static int smem_set = 0;
    const int smem_b = 2 * 128 * 68 * (int)sizeof(float);   /* 69632 B */
    if (!smem_set) {
        cudaFuncSetAttribute(compute_D_kernel,
                             cudaFuncAttributeMaxDynamicSharedMemorySize, smem_b);
        smem_set = 1;
    }

    dim3 gridA(64, NBATCH);
    compute_D_kernel<<<gridA, 256, smem_b>>>(x, y);
    sdtw_pipeline_kernel<<<NBATCH, 1024>>>(out);
}

// round 17
// speedup vs baseline: 1.8595x; 1.0430x over previous
#include <cuda_runtime.h>
#include <math.h>
#include <cstdint>

#define LSEQ   1024
#define NBATCH 64
#define NCH    64
#define NSPG   264           /* step groups per strip: 264*4 = 1056 steps */
#define BIGC   1.0e10f
#define LOG2E  1.4426950408889634f
#define LN2F   0.6931471805599453f

/* Group-packed strip scratch: g_D4[b][w][sp][l][4] holds
   D[32w+l][(4sp+q)-l]*log2(e) for q=0..3. 277 MB. Unwritten slots stay 0. */
__device__ float g_D4[(size_t)NBATCH * 32 * NSPG * 128];

__device__ __forceinline__ float ex2(float z) {
    float r; asm("ex2.approx.f32 %0, %1;" : "=f"(r) : "f"(z)); return r;
}
__device__ __forceinline__ float lg2(float z) {
    float r; asm("lg2.approx.f32 %0, %1;" : "=f"(r) : "f"(z)); return r;
}
__device__ __forceinline__ uint32_t f2tf32(float v) {
    uint32_t r; asm("cvt.rna.tf32.f32 %0, %1;" : "=r"(r) : "f"(v)); return r;
}
/* softmin in base-2 domain: -log2(2^-a + 2^-u + 2^-lf), 3 XU ops (min) */
__device__ __forceinline__ float softmin3(float a, float u, float lf) {
    float mn1 = fminf(a, u);
    float mx1 = fmaxf(a, u);
    float m   = fminf(mn1, lf);
    float M   = fmaxf(mx1, lf);
    float med = fmaxf(mn1, fminf(mx1, lf));
    float e   = 1.0f + ex2(m - med) + ex2(m - M);
    return m - lg2(e);
}

/* ------------------------------------------------------------------ */
/* Kernel A: D = (x2 + y2 - 2*x.y^T) * log2(e) via tf32 mma.sync,     */
/* 128x128 tiles; Dt stride 132 (conflict-free epilogue writes AND     */
/* scatter reads); scatter writes float4 step-groups (STG.128).        */
/* ------------------------------------------------------------------ */
__global__ void __launch_bounds__(256)
compute_D_kernel(const float* __restrict__ x, const float* __restrict__ y) {
    extern __shared__ float sbuf[];       /* 17408 floats = 69632 B */
    __shared__ float sx2[128], sy2[128];

    const int b  = blockIdx.y;
    const int ti = blockIdx.x >> 3;       /* 0..7 */
    const int tj = blockIdx.x & 7;        /* 0..7 */
    const int i0 = ti * 128, j0 = tj * 128;

    float* xs = sbuf;                     /* [128][68] */
    float* ys = sbuf + 128 * 68;          /* [128][68] */

    const int tid = threadIdx.x;
    const float4* xb4 = (const float4*)(x + ((size_t)b * LSEQ + i0) * NCH);
    const float4* yb4 = (const float4*)(y + ((size_t)b * LSEQ + j0) * NCH);

#pragma unroll
    for (int k = 0; k < 8; k++) {
        int e = tid + 256 * k;            /* 0..2047 */
        int r = e >> 4, c4v = e & 15;
        float4 vx = xb4[r * 16 + c4v];
        float4 vy = yb4[r * 16 + c4v];
        vx.x = __uint_as_float(f2tf32(vx.x)); vx.y = __uint_as_float(f2tf32(vx.y));
        vx.z = __uint_as_float(f2tf32(vx.z)); vx.w = __uint_as_float(f2tf32(vx.w));
        vy.x = __uint_as_float(f2tf32(vy.x)); vy.y = __uint_as_float(f2tf32(vy.y));
        vy.z = __uint_as_float(f2tf32(vy.z)); vy.w = __uint_as_float(f2tf32(vy.w));
        *(float4*)&xs[r * 68 + c4v * 4] = vx;
        *(float4*)&ys[r * 68 + c4v * 4] = vy;
    }
    __syncthreads();

    if (tid < 128) {
        float s = 0.f;
#pragma unroll
        for (int c = 0; c < 64; c++) { float v = xs[tid * 68 + c]; s += v * v; }
        sx2[tid] = s;
    } else {
        int r = tid - 128;
        float s = 0.f;
#pragma unroll
        for (int c = 0; c < 64; c++) { float v = ys[r * 68 + c]; s += v * v; }
        sy2[r] = s;
    }
    __syncthreads();

    /* 8 warps: warp wrp owns rows [16wrp, 16wrp+16) x all 128 cols */
    const int wrp  = tid >> 5, lane = tid & 31;
    const int r4   = lane >> 2, c4 = lane & 3;
    const float* As = xs + (wrp * 16) * 68;
    const float* Bs = ys;

    float cc[16][4];
#pragma unroll
    for (int nt = 0; nt < 16; nt++)
#pragma unroll
        for (int q = 0; q < 4; q++) cc[nt][q] = 0.f;

#pragma unroll
    for (int k0 = 0; k0 < 64; k0 += 8) {
        uint32_t a0 = __float_as_uint(As[(r4)     * 68 + k0 + c4]);
        uint32_t a1 = __float_as_uint(As[(r4 + 8) * 68 + k0 + c4]);
        uint32_t a2 = __float_as_uint(As[(r4)     * 68 + k0 + c4 + 4]);
        uint32_t a3 = __float_as_uint(As[(r4 + 8) * 68 + k0 + c4 + 4]);
#pragma unroll
        for (int nt = 0; nt < 16; nt++) {
            uint32_t b0 = __float_as_uint(Bs[(nt * 8 + r4) * 68 + k0 + c4]);
            uint32_t b1 = __float_as_uint(Bs[(nt * 8 + r4) * 68 + k0 + c4 + 4]);
            asm volatile(
                "mma.sync.aligned.m16n8k8.row.col.f32.tf32.tf32.f32 "
                "{%0,%1,%2,%3}, {%4,%5,%6,%7}, {%8,%9}, {%0,%1,%2,%3};"
                : "+f"(cc[nt][0]), "+f"(cc[nt][1]), "+f"(cc[nt][2]), "+f"(cc[nt][3])
                : "r"(a0), "r"(a1), "r"(a2), "r"(a3), "r"(b0), "r"(b1));
        }
    }
    __syncthreads();                  /* xs/ys dead -> reuse as Dt_T */

    float* Dt = sbuf;                 /* Dt_T[jl][il], stride 132 */
    const int row0 = wrp * 16 + r4;
#pragma unroll
    for (int nt = 0; nt < 16; nt++) {
        int colb = nt * 8 + 2 * c4;
        Dt[colb * 132 + row0]           = (sx2[row0]     + sy2[colb]     - 2.0f * cc[nt][0]) * LOG2E;
        Dt[(colb + 1) * 132 + row0]     = (sx2[row0]     + sy2[colb + 1] - 2.0f * cc[nt][1]) * LOG2E;
        Dt[colb * 132 + row0 + 8]       = (sx2[row0 + 8] + sy2[colb]     - 2.0f * cc[nt][2]) * LOG2E;
        Dt[(colb + 1) * 132 + row0 + 8] = (sx2[row0 + 8] + sy2[colb + 1] - 2.0f * cc[nt][3]) * LOG2E;
    }
    __syncthreads();

    /* strip w = 4*ti + h (h=0..3) owns rows 32h..32h+31 of this tile.  */
    /* Step-group G covers so = 4G..4G+3; lane l writes float4 when the */
    /* whole group is tile-interior, else guarded scalar stores.        */
    const int h  = wrp & 3;
    const int w4 = wrp >> 2;          /* 0..1 */
    const size_t gbase = ((size_t)(b * 32 + ti * 4 + h) * NSPG + (j0 >> 2)) * 128;
    for (int G = w4; G < 40; G += 2) {
        const int jl0 = 4 * G - lane;
        float* dst = g_D4 + gbase + (size_t)G * 128 + lane * 4;
        if (jl0 >= 0 && jl0 <= 124) {
            float4 v;
            v.x = Dt[(jl0 + 0) * 132 + 32 * h + lane];
            v.y = Dt[(jl0 + 1) * 132 + 32 * h + lane];
            v.z = Dt[(jl0 + 2) * 132 + 32 * h + lane];
            v.w = Dt[(jl0 + 3) * 132 + 32 * h + lane];
            *(float4*)dst = v;
        } else {
#pragma unroll
            for (int q = 0; q < 4; q++) {
                int jl = jl0 + q;
                if (jl >= 0 && jl < 128)
                    dst[q] = Dt[jl * 132 + 32 * h + lane];
            }
        }
    }
}

/* ------------------------------------------------------------------ */
/* Kernel B: 32 warps x 1 row/lane, barrier-paced, CH=8 / KOFF=5       */
/* (lag 40), unguarded body, float4 D prefetch (2x LDG.128/chunk).     */
/* NEW: ring shifted by 1 (write slot (s-31)&127, read slot s&127) so  */
/* each chunk's 8 boundary values load as 2x LDS.128 up front.         */
/* ------------------------------------------------------------------ */
#define CH      8
#define NCHUNK  132                     /* 132*8 = 1056 >= 1055 steps */
#define KOFF    5
#define NROUNDS (KOFF * 31 + NCHUNK)    /* 287 */

__global__ void __launch_bounds__(1024)
sdtw_pipeline_kernel(float* __restrict__ out) {
    const int b   = blockIdx.x;
    const int tid = threadIdx.x;
    const int w   = tid >> 5;
    const int l   = tid & 31;

    __shared__ __align__(16) float rb[31][128];   /* boundary rings */

    for (int e = tid; e < 31 * 128; e += 1024) ((float*)rb)[e] = BIGC;
    __syncthreads();

    float v1     = BIGC;                            /* left operand  */
    float u_prev = (w == 0 && l == 0) ? 0.0f : BIGC;/* diag operand  */
    float result = 0.0f;

    /* float4 view of D: one group = 32 float4s; lane l owns float4 #l */
    const float4* dp4 = (const float4*)g_D4 + (size_t)(b * 32 + w) * (NSPG * 32) + l;
    float*       rbw = (w < 31) ? rb[w] : rb[0];
    const float* rbr = (w > 0) ? rb[w - 1] : rb[0];

    float dv[CH];
    if (w == 0) {                        /* warp 0 preloads its chunk 0 */
        float4 a0 = dp4[0];
        float4 a1 = dp4[32];
        dv[0] = a0.x; dv[1] = a0.y; dv[2] = a0.z; dv[3] = a0.w;
        dv[4] = a1.x; dv[5] = a1.y; dv[6] = a1.z; dv[7] = a1.w;
    }

    for (int r = 0; r < NROUNDS; r++) {
        const int c  = r - KOFF * w;
        const int cn = c + 1;

        /* prefetch next D chunk: 2 LDG.128 (consumed next round) */
        float4 n0, n1;
        const bool pf = (cn >= 0) && (cn < NCHUNK);
        if (pf) {
            n0 = dp4[(size_t)(2 * cn) * 32];
            n1 = dp4[(size_t)(2 * cn + 1) * 32];
        }

        if (c >= 0 && c < NCHUNK) {
            const int sc = c * CH;
            /* chunk's boundary values: slots sc..sc+7 (8-aligned, no wrap) */
            float bv[CH];
            {
                const float4 q0 = *(const float4*)&rbr[sc & 127];
                const float4 q1 = *(const float4*)&rbr[(sc & 127) + 4];
                bv[0] = q0.x; bv[1] = q0.y; bv[2] = q0.z; bv[3] = q0.w;
                bv[4] = q1.x; bv[5] = q1.y; bv[6] = q1.z; bv[7] = q1.w;
            }
#pragma unroll
            for (int k = 0; k < CH; k++) {
                const int s = sc + k;
                float u = __shfl_up_sync(0xffffffffu, v1, 1);
                if (l == 0) u = (w == 0) ? BIGC : bv[k];
                float nv = dv[k] + softmin3(u_prev, u, v1);
                if (l == 31) {
                    if (w < 31) rbw[(s - 31) & 127] = nv;
                    else if (s == 1054) result = nv;        /* R[1024][1024] */
                }
                v1     = nv;
                u_prev = u;
            }
        }

        if (pf) {
            dv[0] = n0.x; dv[1] = n0.y; dv[2] = n0.z; dv[3] = n0.w;
            dv[4] = n1.x; dv[5] = n1.y; dv[6] = n1.z; dv[7] = n1.w;
        }
        __syncthreads();
    }

    if (w == 31 && l == 31) out[b] = result * LN2F;
}

/* ------------------------------------------------------------------ */
extern "C" void kernel_launch(void* const* d_in, const int* in_sizes, int n_in,
                              void* d_out, int out_size) {
    (void)in_sizes; (void)n_in; (void)out_size;
    const float* x = (const float*)d_in[0];
    const float* y = (const float*)d_in[1];
    float* out = (float*)d_out;

    static int smem_set = 0;
    const int smem_b = 2 * 128 * 68 * (int)sizeof(float);   /* 69632 B */
    if (!smem_set) {
        cudaFuncSetAttribute(compute_D_kernel,
                             cudaFuncAttributeMaxDynamicSharedMemorySize, smem_b);
        smem_set = 1;
    }

    dim3 gridA(64, NBATCH);
    compute_D_kernel<<<gridA, 256, smem_b>>>(x, y);
    sdtw_pipeline_kernel<<<NBATCH, 1024>>>(out);
}